// round 8
// baseline (speedup 1.0000x reference)
#include <cuda_runtime.h>
#include <cuda_bf16.h>
#include <cstdint>

// Problem constants (match reference FEATS / shapes; spatial_shapes input is redundant)
#define BSZ   2
#define NQ    10000
#define DIM   256
#define NH    8
#define NL    4
#define NP    4
#define HD    32
#define NV    13294
#define MTOT  (BSZ * NQ)          // 20000 rows in the GEMM
#define NOUT  384                 // 256 offset outputs + 128 attn outputs

// Compile-time level geometry (FEATS = {100,50,25,13} squares)
__host__ __device__ __forceinline__ constexpr int lvlW(int l) {
    return l == 0 ? 100 : l == 1 ? 50 : l == 2 ? 25 : 13;
}
__host__ __device__ __forceinline__ constexpr int lvlS(int l) {
    return l == 0 ? 0 : l == 1 ? 10000 : l == 2 ? 12500 : 13125;
}

// Scratch (allocation-free rule: __device__ global)
__device__ float g_C[(size_t)MTOT * NOUT];            // GEMM output: [bq][384]

// ---------------------------------------------------------------------------
// Kernel 1: fused projection GEMM  C[bq][o] = query[bq] . W[o] + b[o]
//   o <  256 -> W_off/b_off ; o >= 256 -> W_attn/b_attn
// 64x64 tile, BK=16, 256 threads, 4x4 micro-tile per thread.
// ---------------------------------------------------------------------------
#define BM 64
#define BN 64
#define BK 16

__global__ void __launch_bounds__(256, 4)
proj_gemm_kernel(const float* __restrict__ Q,
                 const float* __restrict__ Woff, const float* __restrict__ boff,
                 const float* __restrict__ Watt, const float* __restrict__ batt)
{
    __shared__ float As[BK][BM + 1];
    __shared__ float Bs[BK][BN + 1];

    const int tid = threadIdx.x;
    const int m0  = blockIdx.x * BM;
    const int n0  = blockIdx.y * BN;
    const int tx  = tid & 15;       // 16 col groups
    const int ty  = tid >> 4;       // 16 row groups
    const int lr  = tid >> 2;       // 0..63 : tile row for loads
    const int lc  = (tid & 3) * 4;  // 0,4,8,12 : k offset (float4)

    float acc[4][4] = {};

    const int gm = m0 + lr;
    const int gn = n0 + lr;
    const float* wrow = (gn < 256) ? (Woff + (size_t)gn * DIM)
                                   : (Watt + (size_t)(gn - 256) * DIM);

    for (int k0 = 0; k0 < DIM; k0 += BK) {
        float4 a4 = make_float4(0.f, 0.f, 0.f, 0.f);
        if (gm < MTOT) a4 = *(const float4*)(Q + (size_t)gm * DIM + k0 + lc);
        As[lc + 0][lr] = a4.x; As[lc + 1][lr] = a4.y;
        As[lc + 2][lr] = a4.z; As[lc + 3][lr] = a4.w;

        float4 b4 = *(const float4*)(wrow + k0 + lc);
        Bs[lc + 0][lr] = b4.x; Bs[lc + 1][lr] = b4.y;
        Bs[lc + 2][lr] = b4.z; Bs[lc + 3][lr] = b4.w;

        __syncthreads();

        #pragma unroll
        for (int kk = 0; kk < BK; ++kk) {
            float a[4], b[4];
            #pragma unroll
            for (int i = 0; i < 4; ++i) a[i] = As[kk][ty * 4 + i];
            #pragma unroll
            for (int j = 0; j < 4; ++j) b[j] = Bs[kk][tx * 4 + j];
            #pragma unroll
            for (int i = 0; i < 4; ++i)
                #pragma unroll
                for (int j = 0; j < 4; ++j)
                    acc[i][j] = fmaf(a[i], b[j], acc[i][j]);
        }
        __syncthreads();
    }

    #pragma unroll
    for (int i = 0; i < 4; ++i) {
        int m = m0 + ty * 4 + i;
        if (m >= MTOT) continue;
        #pragma unroll
        for (int j = 0; j < 4; ++j) {
            int n = n0 + tx * 4 + j;
            float bias = (n < 256) ? boff[n] : batt[n - 256];
            g_C[(size_t)m * NOUT + n] = acc[i][j] + bias;
        }
    }
}

// ---------------------------------------------------------------------------
// Kernel 2 (fused): softmax + sampling locations + bilinear gather + weighted
// accumulation.
// Block: 256 threads = 8 warps. blockIdx.x -> (b,h), blockIdx.y -> 32-query
// chunk. Warp handles one query at a time (lane = channel; location/softmax
// math is lane-redundant via broadcast loads). Corner validity folded into
// weights (w=0 + clamped address) so the 4 loads per point are branch-free.
// Smem transpose gives coalesced channel-major output writes.
// ---------------------------------------------------------------------------
__global__ void __launch_bounds__(256, 8)
sample_kernel(const float* __restrict__ value,
              const float* __restrict__ refp,
              float* __restrict__ out)
{
    __shared__ float sout[32][33];

    const int b    = blockIdx.x >> 3;
    const int h    = blockIdx.x & 7;
    const int q0   = blockIdx.y * 32;
    const int warp = threadIdx.x >> 5;
    const int lane = threadIdx.x & 31;

    // value element: ((b*NV + v)*NH + h)*HD + lane ; per-v stride = NH*HD = 256
    const float* vbase = value + ((size_t)b * NV * NH + h) * HD + lane;

    #pragma unroll
    for (int it = 0; it < 4; ++it) {
        const int ql = it * 8 + warp;
        const int q  = q0 + ql;
        float acc = 0.f;
        if (q < NQ) {
            const int bq = b * NQ + q;
            const float* crow = g_C + (size_t)bq * NOUT;
            const float* rp   = refp + (size_t)bq * NL * 2;

            // softmax over this head's 16 logits (broadcast loads, uniform per warp)
            float lg[16];
            float mx = -1e30f;
            #pragma unroll
            for (int j = 0; j < 16; ++j) {
                lg[j] = __ldg(crow + 256 + h * 16 + j);
                mx = fmaxf(mx, lg[j]);
            }
            float sum = 0.f;
            #pragma unroll
            for (int j = 0; j < 16; ++j) {
                lg[j] = __expf(lg[j] - mx);
                sum += lg[j];
            }
            const float rsum = 1.f / sum;

            #pragma unroll
            for (int lp = 0; lp < 16; ++lp) {
                const int l  = lp >> 2;
                const int p  = lp & 3;
                const int Wl = lvlW(l);
                const int Sl = lvlS(l);
                const float invD = 1.f / (float)Wl;   // square levels: invW == invH

                const float a  = lg[lp] * rsum;
                const float ox = __ldg(crow + h * 32 + l * 8 + p * 2 + 0);
                const float oy = __ldg(crow + h * 32 + l * 8 + p * 2 + 1);
                const float gx = (__ldg(rp + l * 2 + 0) + ox * invD) * 2.f - 1.f;
                const float gy = (__ldg(rp + l * 2 + 1) + oy * invD) * 2.f - 1.f;

                float xf = (gx + 1.f) * (0.5f * (float)Wl) - 0.5f;
                float yf = (gy + 1.f) * (0.5f * (float)Wl) - 0.5f;
                float xfl = floorf(xf), yfl = floorf(yf);
                int   x0 = (int)xfl, y0 = (int)yfl;
                float fx = xf - xfl, fy = yf - yfl;

                const bool vx0 = (unsigned)x0       < (unsigned)Wl;
                const bool vx1 = (unsigned)(x0 + 1) < (unsigned)Wl;
                const bool vy0 = (unsigned)y0       < (unsigned)Wl;
                const bool vy1 = (unsigned)(y0 + 1) < (unsigned)Wl;

                float w00 = (vx0 && vy0) ? a * (1.f - fx) * (1.f - fy) : 0.f;
                float w10 = (vx1 && vy0) ? a * fx * (1.f - fy)         : 0.f;
                float w01 = (vx0 && vy1) ? a * (1.f - fx) * fy         : 0.f;
                float w11 = (vx1 && vy1) ? a * fx * fy                 : 0.f;

                // Clamped (always in-bounds) coordinates; invalid corners have w=0.
                const int x0c = min(max(x0, 0), Wl - 1);
                const int x1c = min(max(x0 + 1, 0), Wl - 1);
                const int y0c = min(max(y0, 0), Wl - 1);
                const int y1c = min(max(y0 + 1, 0), Wl - 1);

                const float* rowb = vbase + (size_t)Sl * 256;
                const float* r0 = rowb + (size_t)y0c * Wl * 256;
                const float* r1 = rowb + (size_t)y1c * Wl * 256;

                float v00 = r0[(size_t)x0c * 256];
                float v10 = r0[(size_t)x1c * 256];
                float v01 = r1[(size_t)x0c * 256];
                float v11 = r1[(size_t)x1c * 256];

                acc = fmaf(w00, v00, acc);
                acc = fmaf(w10, v10, acc);
                acc = fmaf(w01, v01, acc);
                acc = fmaf(w11, v11, acc);
            }
        }
        sout[ql][lane] = acc;
    }
    __syncthreads();

    // Coalesced write: out[b][h*32 + c][q0 + lane]
    const int qw = q0 + lane;
    if (qw < NQ) {
        #pragma unroll
        for (int cc = 0; cc < 4; ++cc) {
            int c = warp * 4 + cc;
            out[((size_t)b * (NH * HD) + h * HD + c) * NQ + qw] = sout[lane][c];
        }
    }
}

// ---------------------------------------------------------------------------
extern "C" void kernel_launch(void* const* d_in, const int* in_sizes, int n_in,
                              void* d_out, int out_size)
{
    const float* query = (const float*)d_in[0];
    const float* value = (const float*)d_in[1];
    const float* refp  = (const float*)d_in[2];
    // d_in[3] spatial_shapes: constants baked in
    const float* Woff  = (const float*)d_in[4];
    const float* boff  = (const float*)d_in[5];
    const float* Watt  = (const float*)d_in[6];
    const float* batt  = (const float*)d_in[7];
    float* out = (float*)d_out;

    dim3 ggrid((MTOT + BM - 1) / BM, NOUT / BN);
    proj_gemm_kernel<<<ggrid, 256>>>(query, Woff, boff, Watt, batt);

    dim3 sgrid(BSZ * NH, (NQ + 31) / 32);
    sample_kernel<<<sgrid, 256>>>(value, refp, out);
}

// round 10
// speedup vs baseline: 1.5199x; 1.5199x over previous
#include <cuda_runtime.h>
#include <cuda_bf16.h>
#include <cstdint>

// Problem constants (match reference FEATS / shapes; spatial_shapes input is redundant)
#define BSZ   2
#define NQ    10000
#define DIM   256
#define NH    8
#define NL    4
#define NP    4
#define HD    32
#define NV    13294
#define MTOT  (BSZ * NQ)          // 20000 rows in the GEMM
#define NOUT  384                 // 256 offset outputs + 128 attn outputs
#define NITEMS (MTOT * NH)        // 160000 (b,q,h) items

// Compile-time level geometry (FEATS = {100,50,25,13} squares)
__host__ __device__ __forceinline__ constexpr int lvlW(int l) {
    return l == 0 ? 100 : l == 1 ? 50 : l == 2 ? 25 : 13;
}
__host__ __device__ __forceinline__ constexpr int lvlS(int l) {
    return l == 0 ? 0 : l == 1 ? 10000 : l == 2 ? 12500 : 13125;
}

// Scratch (allocation-free rule: __device__ globals)
__device__ float  g_C[(size_t)MTOT * NOUT];     // GEMM output: [bq][384]
__device__ float4 g_wgt[(size_t)16 * NITEMS];   // [lp][item] 4 bilinear weights (attn folded in)
__device__ int4   g_ofs[(size_t)16 * NITEMS];   // [lp][item] 4 clamped element offsets (v-index*256)

// ---------------------------------------------------------------------------
// Kernel 1: fused projection GEMM  C[bq][o] = query[bq] . W[o] + b[o]
//   o <  256 -> W_off/b_off ; o >= 256 -> W_attn/b_attn
// 128x64 tile, BK=16, 256 threads, 8x4 micro-tile per thread.
// ---------------------------------------------------------------------------
#define BM 128
#define BN 64
#define BK 16

__global__ void __launch_bounds__(256, 2)
proj_gemm_kernel(const float* __restrict__ Q,
                 const float* __restrict__ Woff, const float* __restrict__ boff,
                 const float* __restrict__ Watt, const float* __restrict__ batt)
{
    __shared__ float As[BK][BM + 4];
    __shared__ float Bs[BK][BN + 4];

    const int tid = threadIdx.x;
    const int m0  = blockIdx.x * BM;
    const int n0  = blockIdx.y * BN;
    const int tx  = tid & 15;       // 16 col groups (x4 cols)
    const int ty  = tid >> 4;       // 16 row groups (x8 rows)
    const int lr  = tid >> 2;       // 0..63
    const int lc  = (tid & 3) * 4;  // 0,4,8,12 : k offset (float4)

    float acc[8][4] = {};

    const int gm0 = m0 + lr;
    const int gm1 = m0 + lr + 64;
    const int gn  = n0 + lr;
    const float* wrow = (gn < 256) ? (Woff + (size_t)gn * DIM)
                                   : (Watt + (size_t)(gn - 256) * DIM);

    for (int k0 = 0; k0 < DIM; k0 += BK) {
        float4 a0 = make_float4(0.f, 0.f, 0.f, 0.f);
        float4 a1 = make_float4(0.f, 0.f, 0.f, 0.f);
        if (gm0 < MTOT) a0 = *(const float4*)(Q + (size_t)gm0 * DIM + k0 + lc);
        if (gm1 < MTOT) a1 = *(const float4*)(Q + (size_t)gm1 * DIM + k0 + lc);
        float4 b4 = *(const float4*)(wrow + k0 + lc);

        As[lc + 0][lr]      = a0.x; As[lc + 1][lr]      = a0.y;
        As[lc + 2][lr]      = a0.z; As[lc + 3][lr]      = a0.w;
        As[lc + 0][lr + 64] = a1.x; As[lc + 1][lr + 64] = a1.y;
        As[lc + 2][lr + 64] = a1.z; As[lc + 3][lr + 64] = a1.w;
        Bs[lc + 0][lr] = b4.x; Bs[lc + 1][lr] = b4.y;
        Bs[lc + 2][lr] = b4.z; Bs[lc + 3][lr] = b4.w;

        __syncthreads();

        #pragma unroll
        for (int kk = 0; kk < BK; ++kk) {
            float a[8], b[4];
            #pragma unroll
            for (int i = 0; i < 8; ++i) a[i] = As[kk][ty * 8 + i];
            #pragma unroll
            for (int j = 0; j < 4; ++j) b[j] = Bs[kk][tx * 4 + j];
            #pragma unroll
            for (int i = 0; i < 8; ++i)
                #pragma unroll
                for (int j = 0; j < 4; ++j)
                    acc[i][j] = fmaf(a[i], b[j], acc[i][j]);
        }
        __syncthreads();
    }

    #pragma unroll
    for (int i = 0; i < 8; ++i) {
        int m = m0 + ty * 8 + i;
        if (m >= MTOT) continue;
        #pragma unroll
        for (int j = 0; j < 4; ++j) {
            int n = n0 + tx * 4 + j;
            float bias = (n < 256) ? boff[n] : batt[n - 256];
            g_C[(size_t)m * NOUT + n] = acc[i][j] + bias;
        }
    }
}

// ---------------------------------------------------------------------------
// Kernel 2: prep — softmax + sampling locations + bilinear weights/offsets.
// One thread per (b,q,h). Writes [lp][item] layout -> coalesced stores.
//   x = ref_x*W + off_x - 0.5  (algebraic fold of the reference transform)
// Out-of-bounds corners: weight=0, offset clamped in-bounds.
// ---------------------------------------------------------------------------
__global__ void __launch_bounds__(256)
prep_kernel(const float* __restrict__ refp)
{
    int idx = blockIdx.x * blockDim.x + threadIdx.x;
    if (idx >= NITEMS) return;
    const int h  = idx & (NH - 1);
    const int bq = idx >> 3;

    const float* crow = g_C + (size_t)bq * NOUT;

    // this head's 32 offsets + 16 logits, vector loads
    float off[32];
    float lg[16];
    #pragma unroll
    for (int j = 0; j < 8; ++j) {
        float4 v = *(const float4*)(crow + h * 32 + j * 4);
        off[j * 4 + 0] = v.x; off[j * 4 + 1] = v.y;
        off[j * 4 + 2] = v.z; off[j * 4 + 3] = v.w;
    }
    #pragma unroll
    for (int j = 0; j < 4; ++j) {
        float4 v = *(const float4*)(crow + 256 + h * 16 + j * 4);
        lg[j * 4 + 0] = v.x; lg[j * 4 + 1] = v.y;
        lg[j * 4 + 2] = v.z; lg[j * 4 + 3] = v.w;
    }

    float mx = -1e30f;
    #pragma unroll
    for (int j = 0; j < 16; ++j) mx = fmaxf(mx, lg[j]);
    float sum = 0.f;
    #pragma unroll
    for (int j = 0; j < 16; ++j) {
        lg[j] = __expf(lg[j] - mx);
        sum += lg[j];
    }
    const float rsum = 1.f / sum;

    const float* rp = refp + (size_t)bq * NL * 2;

    #pragma unroll
    for (int l = 0; l < NL; ++l) {
        const int   Wl   = lvlW(l);
        const int   Sl   = lvlS(l);
        const float invD = 1.f / (float)Wl;
        const float rx   = rp[l * 2 + 0];
        const float ry   = rp[l * 2 + 1];
        #pragma unroll
        for (int p = 0; p < NP; ++p) {
            const int lp = l * 4 + p;
            const float a = lg[lp] * rsum;

            // reference: loc=(ref+off/W)*2-1 ; x=(loc+1)*W/2-0.5  ==  (ref+off/W)*W-0.5
            float xf = (rx + off[l * 8 + p * 2 + 0] * invD) * (float)Wl - 0.5f;
            float yf = (ry + off[l * 8 + p * 2 + 1] * invD) * (float)Wl - 0.5f;
            float xfl = floorf(xf), yfl = floorf(yf);
            int   x0 = (int)xfl, y0 = (int)yfl;
            float fx = xf - xfl, fy = yf - yfl;

            const bool vx0 = (unsigned)x0       < (unsigned)Wl;
            const bool vx1 = (unsigned)(x0 + 1) < (unsigned)Wl;
            const bool vy0 = (unsigned)y0       < (unsigned)Wl;
            const bool vy1 = (unsigned)(y0 + 1) < (unsigned)Wl;

            float4 w;
            w.x = (vx0 && vy0) ? a * (1.f - fx) * (1.f - fy) : 0.f;
            w.y = (vx1 && vy0) ? a * fx * (1.f - fy)         : 0.f;
            w.z = (vx0 && vy1) ? a * (1.f - fx) * fy         : 0.f;
            w.w = (vx1 && vy1) ? a * fx * fy                 : 0.f;

            const int x0c = min(max(x0, 0), Wl - 1);
            const int x1c = min(max(x0 + 1, 0), Wl - 1);
            const int y0c = min(max(y0, 0), Wl - 1);
            const int y1c = min(max(y0 + 1, 0), Wl - 1);

            int4 o;
            o.x = (Sl + y0c * Wl + x0c) * 256;   // element offsets rel. to (b,h,lane) base
            o.y = (Sl + y0c * Wl + x1c) * 256;
            o.z = (Sl + y1c * Wl + x0c) * 256;
            o.w = (Sl + y1c * Wl + x1c) * 256;

            g_wgt[(size_t)lp * NITEMS + idx] = w;
            g_ofs[(size_t)lp * NITEMS + idx] = o;
        }
    }
}

// ---------------------------------------------------------------------------
// Kernel 3: gather + weighted accumulation (all point math precomputed).
// Block: 256 threads = 8 warps. blockIdx.x -> (b,h), blockIdx.y -> 32-query
// chunk. Warp handles one query at a time (lane = channel). Per point:
// 2 uniform 16B loads + 4 scalar gathers + 4 FMAs, 32-bit offsets.
// Smem transpose gives coalesced channel-major output writes.
// ---------------------------------------------------------------------------
__global__ void __launch_bounds__(256, 8)
sample_kernel(const float* __restrict__ value, float* __restrict__ out)
{
    __shared__ float sout[32][33];

    const int b    = blockIdx.x >> 3;
    const int h    = blockIdx.x & 7;
    const int q0   = blockIdx.y * 32;
    const int warp = threadIdx.x >> 5;
    const int lane = threadIdx.x & 31;

    // value element: b*NV*NH*HD + v*256 + h*HD + lane
    const float* vbase = value + ((size_t)b * NV * NH + h) * HD + lane;

    #pragma unroll
    for (int it = 0; it < 4; ++it) {
        const int ql = it * 8 + warp;
        const int q  = q0 + ql;
        float acc = 0.f;
        if (q < NQ) {
            const int item = (b * NQ + q) * NH + h;
            #pragma unroll
            for (int lp = 0; lp < 16; ++lp) {
                const float4 w = __ldg(&g_wgt[(size_t)lp * NITEMS + item]);
                const int4   o = __ldg(&g_ofs[(size_t)lp * NITEMS + item]);
                acc = fmaf(w.x, __ldg(vbase + o.x), acc);
                acc = fmaf(w.y, __ldg(vbase + o.y), acc);
                acc = fmaf(w.z, __ldg(vbase + o.z), acc);
                acc = fmaf(w.w, __ldg(vbase + o.w), acc);
            }
        }
        sout[ql][lane] = acc;
    }
    __syncthreads();

    // Coalesced write: out[b][h*32 + c][q0 + lane]
    const int qw = q0 + lane;
    if (qw < NQ) {
        #pragma unroll
        for (int cc = 0; cc < 4; ++cc) {
            int c = warp * 4 + cc;
            out[((size_t)b * (NH * HD) + h * HD + c) * NQ + qw] = sout[lane][c];
        }
    }
}

// ---------------------------------------------------------------------------
extern "C" void kernel_launch(void* const* d_in, const int* in_sizes, int n_in,
                              void* d_out, int out_size)
{
    const float* query = (const float*)d_in[0];
    const float* value = (const float*)d_in[1];
    const float* refp  = (const float*)d_in[2];
    // d_in[3] spatial_shapes: constants baked in
    const float* Woff  = (const float*)d_in[4];
    const float* boff  = (const float*)d_in[5];
    const float* Watt  = (const float*)d_in[6];
    const float* batt  = (const float*)d_in[7];
    float* out = (float*)d_out;

    dim3 ggrid((MTOT + BM - 1) / BM, NOUT / BN);
    proj_gemm_kernel<<<ggrid, 256>>>(query, Woff, boff, Watt, batt);

    prep_kernel<<<(NITEMS + 255) / 256, 256>>>(refp);

    dim3 sgrid(BSZ * NH, (NQ + 31) / 32);
    sample_kernel<<<sgrid, 256>>>(value, out);
}